// round 14
// baseline (speedup 1.0000x reference)
#include <cuda_runtime.h>
#include <cuda_fp16.h>

// CosineSimilarity: out[e] = <h[src], h[dst]> / (||h[src]|| * ||h[dst]||)
// N=100000, D=128, E=640000.
//
// fp16 normalized table (25.6 MB, L2-resident). Edge pass: 8 lanes/edge,
// 16 edges/warp (4 consecutive per lane-group), vectorized idx loads,
// all 16 row loads issued up front, STG.128 result stores.
// __launch_bounds__(256,8) pins regs <=32 for full occupancy.

#define D_DIM 128
#define MAX_N 100000

__device__ __half g_hn[MAX_N * D_DIM];   // normalized rows, fp16 (25.6 MB)
__device__ int g_idx_is64;               // 1 => int64 indices, 0 => int32

// ---------------------------------------------------------------------------
// Pass 1: one warp per node: sum of squares, warp reduce, write fp16
// normalized row (32 lanes x 8 B, coalesced). One extra warp past N does
// index-width detection: int64 values < 2^31 (LE) have all odd 32-bit words
// zero; for int32 those words are random node ids — 128 samples are exact.
// ---------------------------------------------------------------------------
__global__ void norm_kernel(const float* __restrict__ h,
                            const unsigned int* __restrict__ idx_words, int N) {
    int gw   = (blockIdx.x * blockDim.x + threadIdx.x) >> 5;
    int lane = threadIdx.x & 31;

    if (gw >= N) {
        if (gw == N) {
            unsigned int acc = 0u;
            for (int i = lane; i < 128; i += 32)
                acc |= idx_words[2 * i + 1];
            #pragma unroll
            for (int o = 16; o > 0; o >>= 1)
                acc |= __shfl_xor_sync(0xFFFFFFFFu, acc, o);
            if (lane == 0)
                g_idx_is64 = (acc == 0u) ? 1 : 0;
        }
        return;
    }

    const float4* row = reinterpret_cast<const float4*>(h + (size_t)gw * D_DIM);
    float4 v = __ldg(&row[lane]);
    float ss = v.x * v.x + v.y * v.y + v.z * v.z + v.w * v.w;
    #pragma unroll
    for (int o = 16; o > 0; o >>= 1)
        ss += __shfl_xor_sync(0xFFFFFFFFu, ss, o);

    float inv = 1.0f / fmaxf(sqrtf(ss), 1e-12f);   // uniform across warp

    __half2 h0 = __floats2half2_rn(v.x * inv, v.y * inv);
    __half2 h1 = __floats2half2_rn(v.z * inv, v.w * inv);
    uint2 packed;
    packed.x = *reinterpret_cast<unsigned int*>(&h0);
    packed.y = *reinterpret_cast<unsigned int*>(&h1);
    reinterpret_cast<uint2*>(g_hn + (size_t)gw * D_DIM)[lane] = packed;
}

// ---------------------------------------------------------------------------
// Per-edge fp16 dot with fp32 finish: 8 HFMA2 into 4 half2 accumulators
// (each fp16 half-lane sums only 2 products, |partial| ~ 0.02), one HADD2
// combine level (partials of 4 products, rounding ~4e-6 rms each), then
// convert to fp32 and tree-add.
// ---------------------------------------------------------------------------
__device__ __forceinline__ float dot16(const float4& a0, const float4& a1,
                                       const float4& b0, const float4& b1) {
    const __half2* A0 = reinterpret_cast<const __half2*>(&a0);
    const __half2* A1 = reinterpret_cast<const __half2*>(&a1);
    const __half2* B0 = reinterpret_cast<const __half2*>(&b0);
    const __half2* B1 = reinterpret_cast<const __half2*>(&b1);
    __half2 c0 = __hmul2(A0[0], B0[0]);  c0 = __hfma2(A1[0], B1[0], c0);
    __half2 c1 = __hmul2(A0[1], B0[1]);  c1 = __hfma2(A1[1], B1[1], c1);
    __half2 c2 = __hmul2(A0[2], B0[2]);  c2 = __hfma2(A1[2], B1[2], c2);
    __half2 c3 = __hmul2(A0[3], B0[3]);  c3 = __hfma2(A1[3], B1[3], c3);
    __half2 c01 = __hadd2(c0, c1);
    __half2 c23 = __hadd2(c2, c3);
    float2 f01 = __half22float2(c01);
    float2 f23 = __half22float2(c23);
    return (f01.x + f01.y) + (f23.x + f23.y);
}

// ---------------------------------------------------------------------------
// Pass 2: warp handles 16 edges; lane-group g (8 lanes) handles 4 consecutive
// edges [w*16 + 4g, +4). Indices loaded vectorized (int4 / 2x longlong2),
// all 16 row LDG.128 issued before math (MLP=16/thread), results stored as
// one STG.128 per group. Exit is warp-uniform so full-mask shuffles are safe;
// partial groups take a guarded scalar path (dormant for E % 16 == 0).
// ---------------------------------------------------------------------------
__global__ void __launch_bounds__(256, 8)
edge_kernel(const void* __restrict__ src_raw,
            const void* __restrict__ dst_raw,
            float* __restrict__ out, int E) {
    int w    = (blockIdx.x * blockDim.x + threadIdx.x) >> 5;  // warp id
    int lane = threadIdx.x & 31;
    int g    = lane >> 3;
    int sub  = lane & 7;

    if (w * 16 >= E) return;                  // warp-uniform exit
    int ebase = w * 16 + g * 4;
    bool full = (ebase + 4 <= E);             // whole group in range

    unsigned int si[4], di[4];
    if (full) {
        if (g_idx_is64) {
            const longlong2* S = reinterpret_cast<const longlong2*>(src_raw);
            const longlong2* D = reinterpret_cast<const longlong2*>(dst_raw);
            longlong2 s01 = __ldg(&S[ebase >> 1]);
            longlong2 s23 = __ldg(&S[(ebase >> 1) + 1]);
            longlong2 d01 = __ldg(&D[ebase >> 1]);
            longlong2 d23 = __ldg(&D[(ebase >> 1) + 1]);
            si[0] = (unsigned int)s01.x;  si[1] = (unsigned int)s01.y;
            si[2] = (unsigned int)s23.x;  si[3] = (unsigned int)s23.y;
            di[0] = (unsigned int)d01.x;  di[1] = (unsigned int)d01.y;
            di[2] = (unsigned int)d23.x;  di[3] = (unsigned int)d23.y;
        } else {
            int4 sv = __ldg(&reinterpret_cast<const int4*>(src_raw)[ebase >> 2]);
            int4 dv = __ldg(&reinterpret_cast<const int4*>(dst_raw)[ebase >> 2]);
            si[0] = sv.x;  si[1] = sv.y;  si[2] = sv.z;  si[3] = sv.w;
            di[0] = dv.x;  di[1] = dv.y;  di[2] = dv.z;  di[3] = dv.w;
        }
    } else {
        #pragma unroll
        for (int i = 0; i < 4; i++) {
            int e = ebase + i;
            if (e < E) {
                if (g_idx_is64) {
                    si[i] = (unsigned int)__ldg(&reinterpret_cast<const long long*>(src_raw)[e]);
                    di[i] = (unsigned int)__ldg(&reinterpret_cast<const long long*>(dst_raw)[e]);
                } else {
                    si[i] = (unsigned int)__ldg(&reinterpret_cast<const int*>(src_raw)[e]);
                    di[i] = (unsigned int)__ldg(&reinterpret_cast<const int*>(dst_raw)[e]);
                }
            } else {
                si[i] = 0;  di[i] = 0;
            }
        }
    }

    const char* base = reinterpret_cast<const char*>(g_hn);
    unsigned int lo = (unsigned int)sub * 16u;   // 16 B per lane within a line

    // All 16 row loads up front (row = 256 B = two 128 B lines per group).
    float4 a0[4], a1[4], b0[4], b1[4];
    #pragma unroll
    for (int i = 0; i < 4; i++) {
        const float4* ps = reinterpret_cast<const float4*>(base + (si[i] << 8) + lo);
        const float4* pd = reinterpret_cast<const float4*>(base + (di[i] << 8) + lo);
        a0[i] = ps[0];  a1[i] = ps[8];
        b0[i] = pd[0];  b1[i] = pd[8];
    }

    float r[4];
    #pragma unroll
    for (int i = 0; i < 4; i++) {
        float acc = dot16(a0[i], a1[i], b0[i], b1[i]);
        #pragma unroll
        for (int o = 4; o > 0; o >>= 1)
            acc += __shfl_xor_sync(0xFFFFFFFFu, acc, o);
        r[i] = acc;
    }

    if (sub == 0) {
        if (full) {
            *reinterpret_cast<float4*>(out + ebase) =
                make_float4(r[0], r[1], r[2], r[3]);
        } else {
            #pragma unroll
            for (int i = 0; i < 4; i++)
                if (ebase + i < E) out[ebase + i] = r[i];
        }
    }
}

extern "C" void kernel_launch(void* const* d_in, const int* in_sizes, int n_in,
                              void* d_out, int out_size) {
    const float* h   = (const float*)d_in[0];
    const void*  src = d_in[1];
    const void*  dst = d_in[2];
    float*       out = (float*)d_out;

    int N = in_sizes[0] / D_DIM;   // 100000
    int E = in_sizes[1];           // 640000

    {
        int threads = 256;
        int warps_needed = N + 1;  // +1 warp for index-width detection
        int blocks = (warps_needed * 32 + threads - 1) / threads;
        norm_kernel<<<blocks, threads>>>(h, (const unsigned int*)src, N);
    }
    {
        int threads = 256;
        long long warps_needed = ((long long)E + 15) / 16;
        int blocks = (int)((warps_needed * 32 + threads - 1) / threads);
        edge_kernel<<<blocks, threads>>>(src, dst, out, E);
    }
}